// round 1
// baseline (speedup 1.0000x reference)
#include <cuda_runtime.h>
#include <math.h>

#define BATCH 4
#define SEQ 2048
#define DMODEL 1024
#define HEADS 16
#define DEPTH 64

// Scratch (module-load allocated, zero-init; no runtime allocation).
__device__ float g_q[BATCH * SEQ * DMODEL];
__device__ float g_k[BATCH * SEQ * DMODEL];
__device__ float g_v[BATCH * SEQ * DMODEL];
__device__ float g_attn[BATCH * SEQ * DMODEL];

// ---------------------------------------------------------------------------
// GEMM: C[m,n] = sum_k A[m,k] * W[n,k] + bias[n]
// A: [8192, 1024] row-major, W: [1024, 1024] row-major (we need X @ W^T).
// headSplit=1: write to [B][H][S][64] layout; headSplit=0: plain [M, 1024].
// 128x128 tile, BK=8, 256 threads, 8x8 register blocking.
// ---------------------------------------------------------------------------
__global__ __launch_bounds__(256) void gemm_bias_kernel(
    const float* __restrict__ A, const float* __restrict__ W,
    const float* __restrict__ bias, float* __restrict__ C, int headSplit)
{
    const int K = DMODEL;
    __shared__ float As[8][128];
    __shared__ float Bs[8][128];

    const int tid = threadIdx.x;
    const int m0 = blockIdx.y * 128;
    const int n0 = blockIdx.x * 128;
    const int tm = tid >> 4;        // 0..15
    const int tn = tid & 15;        // 0..15

    const int loadRow = tid >> 1;          // 0..127
    const int loadCol = (tid & 1) * 4;     // 0 or 4

    const float* Aptr = A + (size_t)(m0 + loadRow) * K + loadCol;
    const float* Wptr = W + (size_t)(n0 + loadRow) * K + loadCol;

    float acc[8][8];
    #pragma unroll
    for (int i = 0; i < 8; i++)
        #pragma unroll
        for (int j = 0; j < 8; j++) acc[i][j] = 0.0f;

    for (int k0 = 0; k0 < K; k0 += 8) {
        float4 av = *(const float4*)(Aptr + k0);
        float4 bv = *(const float4*)(Wptr + k0);
        As[loadCol + 0][loadRow] = av.x;
        As[loadCol + 1][loadRow] = av.y;
        As[loadCol + 2][loadRow] = av.z;
        As[loadCol + 3][loadRow] = av.w;
        Bs[loadCol + 0][loadRow] = bv.x;
        Bs[loadCol + 1][loadRow] = bv.y;
        Bs[loadCol + 2][loadRow] = bv.z;
        Bs[loadCol + 3][loadRow] = bv.w;
        __syncthreads();

        #pragma unroll
        for (int kk = 0; kk < 8; kk++) {
            float4 a0 = *(const float4*)&As[kk][tm * 8];
            float4 a1 = *(const float4*)&As[kk][tm * 8 + 4];
            float4 b0 = *(const float4*)&Bs[kk][tn * 8];
            float4 b1 = *(const float4*)&Bs[kk][tn * 8 + 4];
            float a[8] = {a0.x, a0.y, a0.z, a0.w, a1.x, a1.y, a1.z, a1.w};
            float b[8] = {b0.x, b0.y, b0.z, b0.w, b1.x, b1.y, b1.z, b1.w};
            #pragma unroll
            for (int i = 0; i < 8; i++)
                #pragma unroll
                for (int j = 0; j < 8; j++)
                    acc[i][j] = fmaf(a[i], b[j], acc[i][j]);
        }
        __syncthreads();
    }

    #pragma unroll
    for (int i = 0; i < 8; i++) {
        const int m = m0 + tm * 8 + i;
        const int b = m >> 11;           // m / SEQ
        const int s = m & (SEQ - 1);
        #pragma unroll
        for (int j = 0; j < 8; j++) {
            const int n = n0 + tn * 8 + j;
            float val = acc[i][j] + bias[n];
            if (headSplit) {
                const int h = n >> 6;
                const int d = n & 63;
                C[((size_t)(b * HEADS + h) * SEQ + s) * DEPTH + d] = val;
            } else {
                C[(size_t)m * DMODEL + n] = val;
            }
        }
    }
}

// ---------------------------------------------------------------------------
// Flash attention, causal, fp32.
// Grid: (S/64, B*H). Block: 256 threads (16x16).
// Q/K/V scratch layout: [B*H][S][64].
// Thread (ty,tx): rows ty*4..+3 of the 64-row q tile, cols/depth tx*4..+3.
// smem: Qts[d][r], Kts[d][c] (transposed, d-major), Vs[c][d], Ps[r][68-pad].
// ---------------------------------------------------------------------------
#define PS_LD 68
__global__ __launch_bounds__(256) void attn_kernel(
    const float* __restrict__ Q, const float* __restrict__ K,
    const float* __restrict__ V, float* __restrict__ O)
{
    extern __shared__ float sm[];
    float* Qts = sm;            // 64*64
    float* Kts = sm + 4096;     // 64*64
    float* Vs  = sm + 8192;     // 64*64
    float* Ps  = sm + 12288;    // 64*PS_LD

    const int tid = threadIdx.x;
    const int ty = tid >> 4;    // 0..15
    const int tx = tid & 15;    // 0..15
    const int qt = blockIdx.x;
    const int bh = blockIdx.y;
    const int qbase = qt * 64;

    const float* Qb = Q + (size_t)bh * SEQ * DEPTH;
    const float* Kb = K + (size_t)bh * SEQ * DEPTH;
    const float* Vb = V + (size_t)bh * SEQ * DEPTH;

    // Load Q tile transposed: Qts[d*64 + r]
    {
        const int r = tid >> 2;            // 0..63
        const int d0 = (tid & 3) * 16;     // 0,16,32,48
        const float* src = Qb + (size_t)(qbase + r) * DEPTH + d0;
        #pragma unroll
        for (int i = 0; i < 16; i += 4) {
            float4 v4 = *(const float4*)(src + i);
            Qts[(d0 + i + 0) * 64 + r] = v4.x;
            Qts[(d0 + i + 1) * 64 + r] = v4.y;
            Qts[(d0 + i + 2) * 64 + r] = v4.z;
            Qts[(d0 + i + 3) * 64 + r] = v4.w;
        }
    }

    float m_i[4], l_i[4], o[4][4];
    #pragma unroll
    for (int i = 0; i < 4; i++) {
        m_i[i] = -INFINITY;
        l_i[i] = 0.0f;
        #pragma unroll
        for (int j = 0; j < 4; j++) o[i][j] = 0.0f;
    }

    const float scale = 0.125f;   // 1/sqrt(64)

    for (int kt = 0; kt <= qt; kt++) {
        __syncthreads();  // previous iter's readers of Kts/Vs/Ps are done
        // Load K tile transposed + V tile natural
        {
            const int r = tid >> 2;
            const int d0 = (tid & 3) * 16;
            const float* ksrc = Kb + (size_t)(kt * 64 + r) * DEPTH + d0;
            const float* vsrc = Vb + (size_t)(kt * 64 + r) * DEPTH + d0;
            #pragma unroll
            for (int i = 0; i < 16; i += 4) {
                float4 kv = *(const float4*)(ksrc + i);
                Kts[(d0 + i + 0) * 64 + r] = kv.x;
                Kts[(d0 + i + 1) * 64 + r] = kv.y;
                Kts[(d0 + i + 2) * 64 + r] = kv.z;
                Kts[(d0 + i + 3) * 64 + r] = kv.w;
                *(float4*)&Vs[r * 64 + d0 + i] = *(const float4*)(vsrc + i);
            }
        }
        __syncthreads();

        // S = Q K^T (64x64x64 per block; this thread: 4x4)
        float s[4][4];
        #pragma unroll
        for (int i = 0; i < 4; i++)
            #pragma unroll
            for (int j = 0; j < 4; j++) s[i][j] = 0.0f;

        #pragma unroll 8
        for (int d = 0; d < 64; d++) {
            float4 qv = *(const float4*)&Qts[d * 64 + ty * 4];
            float4 kv = *(const float4*)&Kts[d * 64 + tx * 4];
            float qa[4] = {qv.x, qv.y, qv.z, qv.w};
            float ka[4] = {kv.x, kv.y, kv.z, kv.w};
            #pragma unroll
            for (int i = 0; i < 4; i++)
                #pragma unroll
                for (int j = 0; j < 4; j++)
                    s[i][j] = fmaf(qa[i], ka[j], s[i][j]);
        }

        // scale + causal mask (diagonal tile only)
        #pragma unroll
        for (int i = 0; i < 4; i++)
            #pragma unroll
            for (int j = 0; j < 4; j++) s[i][j] *= scale;
        if (kt == qt) {
            #pragma unroll
            for (int i = 0; i < 4; i++) {
                const int rr = ty * 4 + i;
                #pragma unroll
                for (int j = 0; j < 4; j++) {
                    const int cc = tx * 4 + j;
                    if (cc > rr) s[i][j] = -1e30f;
                }
            }
        }

        // online softmax update per row (16 lanes share each row)
        #pragma unroll
        for (int i = 0; i < 4; i++) {
            float mx = fmaxf(fmaxf(s[i][0], s[i][1]), fmaxf(s[i][2], s[i][3]));
            #pragma unroll
            for (int off = 8; off >= 1; off >>= 1)
                mx = fmaxf(mx, __shfl_xor_sync(0xffffffffu, mx, off));
            const float nm = fmaxf(m_i[i], mx);
            float p[4], ps = 0.0f;
            #pragma unroll
            for (int j = 0; j < 4; j++) {
                p[j] = __expf(s[i][j] - nm);
                ps += p[j];
            }
            #pragma unroll
            for (int off = 8; off >= 1; off >>= 1)
                ps += __shfl_xor_sync(0xffffffffu, ps, off);
            const float alpha = __expf(m_i[i] - nm);
            l_i[i] = l_i[i] * alpha + ps;
            m_i[i] = nm;
            #pragma unroll
            for (int j = 0; j < 4; j++) {
                o[i][j] *= alpha;
                Ps[(ty * 4 + i) * PS_LD + tx * 4 + j] = p[j];
            }
        }
        __syncthreads();

        // O += P V  (64x64x64 per block; this thread: 4 rows x 4 depth)
        #pragma unroll 4
        for (int kc4 = 0; kc4 < 64; kc4 += 4) {
            float4 pr[4];
            #pragma unroll
            for (int i = 0; i < 4; i++)
                pr[i] = *(const float4*)&Ps[(ty * 4 + i) * PS_LD + kc4];
            #pragma unroll
            for (int t = 0; t < 4; t++) {
                float4 vv = *(const float4*)&Vs[(kc4 + t) * 64 + tx * 4];
                float va[4] = {vv.x, vv.y, vv.z, vv.w};
                #pragma unroll
                for (int i = 0; i < 4; i++) {
                    const float pv = (t == 0) ? pr[i].x : (t == 1) ? pr[i].y
                                   : (t == 2) ? pr[i].z : pr[i].w;
                    #pragma unroll
                    for (int j = 0; j < 4; j++)
                        o[i][j] = fmaf(pv, va[j], o[i][j]);
                }
            }
        }
    }

    // epilogue: normalize + write merged-head [B][S][1024]
    const int b = bh >> 4;
    const int h = bh & 15;
    #pragma unroll
    for (int i = 0; i < 4; i++) {
        const int r = qbase + ty * 4 + i;
        const float inv = 1.0f / l_i[i];
        #pragma unroll
        for (int j = 0; j < 4; j++) {
            O[((size_t)b * SEQ + r) * DMODEL + h * DEPTH + tx * 4 + j] = o[i][j] * inv;
        }
    }
}

// ---------------------------------------------------------------------------
extern "C" void kernel_launch(void* const* d_in, const int* in_sizes, int n_in,
                              void* d_out, int out_size)
{
    const float* q    = (const float*)d_in[0];
    const float* k    = (const float*)d_in[1];
    const float* v    = (const float*)d_in[2];
    const float* wq_w = (const float*)d_in[3];
    const float* wq_b = (const float*)d_in[4];
    const float* wk_w = (const float*)d_in[5];
    const float* wk_b = (const float*)d_in[6];
    const float* wv_w = (const float*)d_in[7];
    const float* wv_b = (const float*)d_in[8];
    const float* dw   = (const float*)d_in[9];
    const float* db   = (const float*)d_in[10];
    float* out = (float*)d_out;

    float *gq, *gk, *gv, *ga;
    cudaGetSymbolAddress((void**)&gq, g_q);
    cudaGetSymbolAddress((void**)&gk, g_k);
    cudaGetSymbolAddress((void**)&gv, g_v);
    cudaGetSymbolAddress((void**)&ga, g_attn);

    const int attn_smem = (4096 * 3 + 64 * PS_LD) * (int)sizeof(float);  // 66560 B
    cudaFuncSetAttribute(attn_kernel,
                         cudaFuncAttributeMaxDynamicSharedMemorySize, attn_smem);

    dim3 gemmGrid(DMODEL / 128, (BATCH * SEQ) / 128);  // (8, 64)
    gemm_bias_kernel<<<gemmGrid, 256>>>(q, wq_w, wq_b, gq, 1);
    gemm_bias_kernel<<<gemmGrid, 256>>>(k, wk_w, wk_b, gk, 1);
    gemm_bias_kernel<<<gemmGrid, 256>>>(v, wv_w, wv_b, gv, 1);

    dim3 attnGrid(SEQ / 64, BATCH * HEADS);            // (32, 64)
    attn_kernel<<<attnGrid, 256, attn_smem>>>(gq, gk, gv, ga);

    gemm_bias_kernel<<<gemmGrid, 256>>>(ga, dw, db, out, 0);
}

// round 6
// speedup vs baseline: 1.9090x; 1.9090x over previous
#include <cuda_runtime.h>
#include <cuda_bf16.h>
#include <cstdint>
#include <math.h>

#define BATCH 4
#define SEQ 2048
#define DMODEL 1024
#define HEADS 16
#define DEPTH 64

// Scratch (module-load allocated; no runtime allocation).
__device__ float g_q[BATCH * SEQ * DMODEL];
__device__ float g_k[BATCH * SEQ * DMODEL];
__device__ float g_v[BATCH * SEQ * DMODEL];
__device__ float g_attn[BATCH * SEQ * DMODEL];

// ===========================================================================
// bf16 split-precision GEMM on mma.sync (compute_100-safe; no tcgen05).
// C[m,n] = sum_k A[m,k]*W[n,k] + bias[n]
// A:[8192,1024] row-major, W:[1024,1024] row-major (both K-contiguous).
// x = hi + lo (bf16 each); C ~= Ahi*Whi + Ahi*Wlo + Alo*Whi  (lo*lo dropped).
// Tiles: 128x128x32, 256 threads, 8 warps as 2(M) x 4(N), warp tile 64x32.
// mma.sync.m16n8k16: per warp 4 m-tiles x 4 n-tiles x 2 k-steps x 3 products.
// ===========================================================================
#define BM 128
#define BN 128
#define BK 32
#define NCHUNK (DMODEL / BK)      // 32
#define SKS 40                    // smem row stride (bf16) -> conflict-free frags
#define PLANE (128 * SKS)         // 5120 bf16 per plane
#define GEMM_SMEM (2 * 4 * PLANE * 2)   // 2 stages * {Ah,Al,Bh,Bl} * 2B = 81920

__device__ __forceinline__ void mma_bf16(float* c, uint32_t a0, uint32_t a1,
                                         uint32_t a2, uint32_t a3,
                                         uint32_t b0, uint32_t b1) {
    asm volatile(
        "mma.sync.aligned.m16n8k16.row.col.f32.bf16.bf16.f32 "
        "{%0,%1,%2,%3},{%4,%5,%6,%7},{%8,%9},{%0,%1,%2,%3};"
        : "+f"(c[0]), "+f"(c[1]), "+f"(c[2]), "+f"(c[3])
        : "r"(a0), "r"(a1), "r"(a2), "r"(a3), "r"(b0), "r"(b1));
}

// Convert one float4 (4 consecutive k) into hi/lo bf16 pairs and store.
__device__ __forceinline__ void cvt_store(float4 x, __nv_bfloat16* hi,
                                          __nv_bfloat16* lo, int idx) {
    __nv_bfloat16 h0 = __float2bfloat16(x.x);
    __nv_bfloat16 h1 = __float2bfloat16(x.y);
    __nv_bfloat16 h2 = __float2bfloat16(x.z);
    __nv_bfloat16 h3 = __float2bfloat16(x.w);
    __nv_bfloat16 l0 = __float2bfloat16(x.x - __bfloat162float(h0));
    __nv_bfloat16 l1 = __float2bfloat16(x.y - __bfloat162float(h1));
    __nv_bfloat16 l2 = __float2bfloat16(x.z - __bfloat162float(h2));
    __nv_bfloat16 l3 = __float2bfloat16(x.w - __bfloat162float(h3));
    __nv_bfloat162 hp0; hp0.x = h0; hp0.y = h1;
    __nv_bfloat162 hp1; hp1.x = h2; hp1.y = h3;
    __nv_bfloat162 lp0; lp0.x = l0; lp0.y = l1;
    __nv_bfloat162 lp1; lp1.x = l2; lp1.y = l3;
    *(__nv_bfloat162*)(hi + idx)     = hp0;
    *(__nv_bfloat162*)(hi + idx + 2) = hp1;
    *(__nv_bfloat162*)(lo + idx)     = lp0;
    *(__nv_bfloat162*)(lo + idx + 2) = lp1;
}

__device__ __forceinline__ void store_c(float* __restrict__ C, int m, int n,
                                        float v0, float v1, int headSplit) {
    float2 t; t.x = v0; t.y = v1;
    if (headSplit) {
        const int b = m >> 11, s = m & (SEQ - 1);
        const int h = n >> 6, d = n & 63;
        *(float2*)&C[(((size_t)(b * HEADS + h) * SEQ + s) * DEPTH) + d] = t;
    } else {
        *(float2*)&C[(size_t)m * DMODEL + n] = t;
    }
}

__global__ __launch_bounds__(256, 1)
void gemm_tc(const float* __restrict__ A, const float* __restrict__ W,
             const float* __restrict__ bias, float* __restrict__ C,
             int headSplit)
{
    extern __shared__ __nv_bfloat16 sm[];
    // plane p of stage s at sm + (s*4+p)*PLANE;  p: 0=Ah 1=Al 2=Bh 3=Bl
    const int tid = threadIdx.x;
    const int lane = tid & 31;
    const int wid = tid >> 5;
    const int wm = (wid >> 2) * 64;    // warp M base within tile
    const int wn = (wid & 3) * 32;     // warp N base within tile
    const int m0 = blockIdx.y * BM;
    const int n0 = blockIdx.x * BN;

    float acc[4][4][4];
    #pragma unroll
    for (int mi = 0; mi < 4; mi++)
        #pragma unroll
        for (int ni = 0; ni < 4; ni++)
            #pragma unroll
            for (int t = 0; t < 4; t++) acc[mi][ni][t] = 0.0f;

    // ---- chunk 0 direct to stage 0 ----
    {
        __nv_bfloat16* Ah = sm;
        __nv_bfloat16* Al = sm + PLANE;
        __nv_bfloat16* Bh = sm + 2 * PLANE;
        __nv_bfloat16* Bl = sm + 3 * PLANE;
        #pragma unroll
        for (int i = 0; i < 4; i++) {
            const int pos = tid + (i << 8);
            const int row = pos >> 3, f4 = pos & 7;
            float4 xa = *(const float4*)(A + (size_t)(m0 + row) * DMODEL + f4 * 4);
            float4 xb = *(const float4*)(W + (size_t)(n0 + row) * DMODEL + f4 * 4);
            cvt_store(xa, Ah, Al, row * SKS + f4 * 4);
            cvt_store(xb, Bh, Bl, row * SKS + f4 * 4);
        }
    }
    __syncthreads();

    float4 regA[4], regB[4];
    for (int c = 0; c < NCHUNK; c++) {
        const int s = c & 1;
        if (c + 1 < NCHUNK) {
            const int k0 = (c + 1) * BK;
            #pragma unroll
            for (int i = 0; i < 4; i++) {
                const int pos = tid + (i << 8);
                const int row = pos >> 3, f4 = pos & 7;
                regA[i] = *(const float4*)(A + (size_t)(m0 + row) * DMODEL + k0 + f4 * 4);
                regB[i] = *(const float4*)(W + (size_t)(n0 + row) * DMODEL + k0 + f4 * 4);
            }
        }

        const __nv_bfloat16* Ah = sm + (s * 4 + 0) * PLANE;
        const __nv_bfloat16* Al = sm + (s * 4 + 1) * PLANE;
        const __nv_bfloat16* Bh = sm + (s * 4 + 2) * PLANE;
        const __nv_bfloat16* Bl = sm + (s * 4 + 3) * PLANE;

        #pragma unroll
        for (int ks = 0; ks < BK; ks += 16) {
            const int col = ks + (lane & 3) * 2;
            uint32_t ah[4][4], al[4][4], bh[4][2], bl[4][2];
            #pragma unroll
            for (int mi = 0; mi < 4; mi++) {
                const int r = wm + mi * 16 + (lane >> 2);
                ah[mi][0] = *(const uint32_t*)&Ah[r * SKS + col];
                ah[mi][1] = *(const uint32_t*)&Ah[(r + 8) * SKS + col];
                ah[mi][2] = *(const uint32_t*)&Ah[r * SKS + col + 8];
                ah[mi][3] = *(const uint32_t*)&Ah[(r + 8) * SKS + col + 8];
                al[mi][0] = *(const uint32_t*)&Al[r * SKS + col];
                al[mi][1] = *(const uint32_t*)&Al[(r + 8) * SKS + col];
                al[mi][2] = *(const uint32_t*)&Al[r * SKS + col + 8];
                al[mi][3] = *(const uint32_t*)&Al[(r + 8) * SKS + col + 8];
            }
            #pragma unroll
            for (int ni = 0; ni < 4; ni++) {
                const int n = wn + ni * 8 + (lane >> 2);
                bh[ni][0] = *(const uint32_t*)&Bh[n * SKS + col];
                bh[ni][1] = *(const uint32_t*)&Bh[n * SKS + col + 8];
                bl[ni][0] = *(const uint32_t*)&Bl[n * SKS + col];
                bl[ni][1] = *(const uint32_t*)&Bl[n * SKS + col + 8];
            }
            #pragma unroll
            for (int mi = 0; mi < 4; mi++)
                #pragma unroll
                for (int ni = 0; ni < 4; ni++) {
                    mma_bf16(acc[mi][ni], ah[mi][0], ah[mi][1], ah[mi][2], ah[mi][3],
                             bh[ni][0], bh[ni][1]);
                    mma_bf16(acc[mi][ni], ah[mi][0], ah[mi][1], ah[mi][2], ah[mi][3],
                             bl[ni][0], bl[ni][1]);
                    mma_bf16(acc[mi][ni], al[mi][0], al[mi][1], al[mi][2], al[mi][3],
                             bh[ni][0], bh[ni][1]);
                }
        }
        __syncthreads();
        if (c + 1 < NCHUNK) {
            const int s2 = (c + 1) & 1;
            __nv_bfloat16* Ah2 = sm + (s2 * 4 + 0) * PLANE;
            __nv_bfloat16* Al2 = sm + (s2 * 4 + 1) * PLANE;
            __nv_bfloat16* Bh2 = sm + (s2 * 4 + 2) * PLANE;
            __nv_bfloat16* Bl2 = sm + (s2 * 4 + 3) * PLANE;
            #pragma unroll
            for (int i = 0; i < 4; i++) {
                const int pos = tid + (i << 8);
                const int row = pos >> 3, f4 = pos & 7;
                cvt_store(regA[i], Ah2, Al2, row * SKS + f4 * 4);
                cvt_store(regB[i], Bh2, Bl2, row * SKS + f4 * 4);
            }
            __syncthreads();
        }
    }

    // ---- epilogue: C frags -> global (+bias) ----
    #pragma unroll
    for (int mi = 0; mi < 4; mi++) {
        const int r = m0 + wm + mi * 16 + (lane >> 2);
        #pragma unroll
        for (int ni = 0; ni < 4; ni++) {
            const int n = n0 + wn + ni * 8 + (lane & 3) * 2;
            const float b0 = bias[n], b1 = bias[n + 1];
            store_c(C, r,     n, acc[mi][ni][0] + b0, acc[mi][ni][1] + b1, headSplit);
            store_c(C, r + 8, n, acc[mi][ni][2] + b0, acc[mi][ni][3] + b1, headSplit);
        }
    }
}

// ===========================================================================
// Flash attention, causal, fp32 (verified in R0; unchanged)
// ===========================================================================
#define PS_LD 68
__global__ __launch_bounds__(256) void attn_kernel(
    const float* __restrict__ Q, const float* __restrict__ K,
    const float* __restrict__ V, float* __restrict__ O)
{
    extern __shared__ float smf[];
    float* Qts = smf;            // 64*64
    float* Kts = smf + 4096;     // 64*64
    float* Vs  = smf + 8192;     // 64*64
    float* Ps  = smf + 12288;    // 64*PS_LD

    const int tid = threadIdx.x;
    const int ty = tid >> 4;
    const int tx = tid & 15;
    const int qt = blockIdx.x;
    const int bh = blockIdx.y;
    const int qbase = qt * 64;

    const float* Qb = Q + (size_t)bh * SEQ * DEPTH;
    const float* Kb = K + (size_t)bh * SEQ * DEPTH;
    const float* Vb = V + (size_t)bh * SEQ * DEPTH;

    {
        const int r = tid >> 2;
        const int d0 = (tid & 3) * 16;
        const float* src = Qb + (size_t)(qbase + r) * DEPTH + d0;
        #pragma unroll
        for (int i = 0; i < 16; i += 4) {
            float4 v4 = *(const float4*)(src + i);
            Qts[(d0 + i + 0) * 64 + r] = v4.x;
            Qts[(d0 + i + 1) * 64 + r] = v4.y;
            Qts[(d0 + i + 2) * 64 + r] = v4.z;
            Qts[(d0 + i + 3) * 64 + r] = v4.w;
        }
    }

    float m_i[4], l_i[4], o[4][4];
    #pragma unroll
    for (int i = 0; i < 4; i++) {
        m_i[i] = -INFINITY;
        l_i[i] = 0.0f;
        #pragma unroll
        for (int j = 0; j < 4; j++) o[i][j] = 0.0f;
    }

    const float scale = 0.125f;

    for (int kt = 0; kt <= qt; kt++) {
        __syncthreads();
        {
            const int r = tid >> 2;
            const int d0 = (tid & 3) * 16;
            const float* ksrc = Kb + (size_t)(kt * 64 + r) * DEPTH + d0;
            const float* vsrc = Vb + (size_t)(kt * 64 + r) * DEPTH + d0;
            #pragma unroll
            for (int i = 0; i < 16; i += 4) {
                float4 kv = *(const float4*)(ksrc + i);
                Kts[(d0 + i + 0) * 64 + r] = kv.x;
                Kts[(d0 + i + 1) * 64 + r] = kv.y;
                Kts[(d0 + i + 2) * 64 + r] = kv.z;
                Kts[(d0 + i + 3) * 64 + r] = kv.w;
                *(float4*)&Vs[r * 64 + d0 + i] = *(const float4*)(vsrc + i);
            }
        }
        __syncthreads();

        float s[4][4];
        #pragma unroll
        for (int i = 0; i < 4; i++)
            #pragma unroll
            for (int j = 0; j < 4; j++) s[i][j] = 0.0f;

        #pragma unroll 8
        for (int d = 0; d < 64; d++) {
            float4 qv = *(const float4*)&Qts[d * 64 + ty * 4];
            float4 kv = *(const float4*)&Kts[d * 64 + tx * 4];
            float a[4] = {qv.x, qv.y, qv.z, qv.w};
            float bb[4] = {kv.x, kv.y, kv.z, kv.w};
            #pragma unroll
            for (int i = 0; i < 4; i++)
                #pragma unroll
                for (int j = 0; j < 4; j++)
                    s[i][j] = fmaf(a[i], bb[j], s[i][j]);
        }

        #pragma unroll
        for (int i = 0; i < 4; i++)
            #pragma unroll
            for (int j = 0; j < 4; j++) s[i][j] *= scale;
        if (kt == qt) {
            #pragma unroll
            for (int i = 0; i < 4; i++) {
                const int rr = ty * 4 + i;
                #pragma unroll
                for (int j = 0; j < 4; j++) {
                    const int cc = tx * 4 + j;
                    if (cc > rr) s[i][j] = -1e30f;
                }
            }
        }

        #pragma unroll
        for (int i = 0; i < 4; i++) {
            float mx = fmaxf(fmaxf(s[i][0], s[i][1]), fmaxf(s[i][2], s[i][3]));
            #pragma unroll
            for (int off = 8; off >= 1; off >>= 1)
                mx = fmaxf(mx, __shfl_xor_sync(0xffffffffu, mx, off));
            const float nm = fmaxf(m_i[i], mx);
            float p[4], ps = 0.0f;
            #pragma unroll
            for (int j = 0; j < 4; j++) {
                p[j] = __expf(s[i][j] - nm);
                ps += p[j];
            }
            #pragma unroll
            for (int off = 8; off >= 1; off >>= 1)
                ps += __shfl_xor_sync(0xffffffffu, ps, off);
            const float alpha = __expf(m_i[i] - nm);
            l_i[i] = l_i[i] * alpha + ps;
            m_i[i] = nm;
            #pragma unroll
            for (int j = 0; j < 4; j++) {
                o[i][j] *= alpha;
                Ps[(ty * 4 + i) * PS_LD + tx * 4 + j] = p[j];
            }
        }
        __syncthreads();

        #pragma unroll 4
        for (int kc4 = 0; kc4 < 64; kc4 += 4) {
            float4 pr[4];
            #pragma unroll
            for (int i = 0; i < 4; i++)
                pr[i] = *(const float4*)&Ps[(ty * 4 + i) * PS_LD + kc4];
            #pragma unroll
            for (int t = 0; t < 4; t++) {
                float4 vv = *(const float4*)&Vs[(kc4 + t) * 64 + tx * 4];
                float va[4] = {vv.x, vv.y, vv.z, vv.w};
                #pragma unroll
                for (int i = 0; i < 4; i++) {
                    const float pv = (t == 0) ? pr[i].x : (t == 1) ? pr[i].y
                                   : (t == 2) ? pr[i].z : pr[i].w;
                    #pragma unroll
                    for (int j = 0; j < 4; j++)
                        o[i][j] = fmaf(pv, va[j], o[i][j]);
                }
            }
        }
    }

    const int b = bh >> 4;
    const int h = bh & 15;
    #pragma unroll
    for (int i = 0; i < 4; i++) {
        const int r = qbase + ty * 4 + i;
        const float inv = 1.0f / l_i[i];
        #pragma unroll
        for (int j = 0; j < 4; j++) {
            O[((size_t)b * SEQ + r) * DMODEL + h * DEPTH + tx * 4 + j] = o[i][j] * inv;
        }
    }
}

// ===========================================================================
extern "C" void kernel_launch(void* const* d_in, const int* in_sizes, int n_in,
                              void* d_out, int out_size)
{
    const float* q    = (const float*)d_in[0];
    const float* k    = (const float*)d_in[1];
    const float* v    = (const float*)d_in[2];
    const float* wq_w = (const float*)d_in[3];
    const float* wq_b = (const float*)d_in[4];
    const float* wk_w = (const float*)d_in[5];
    const float* wk_b = (const float*)d_in[6];
    const float* wv_w = (const float*)d_in[7];
    const float* wv_b = (const float*)d_in[8];
    const float* dw   = (const float*)d_in[9];
    const float* db   = (const float*)d_in[10];
    float* out = (float*)d_out;

    float *gq, *gk, *gv, *ga;
    cudaGetSymbolAddress((void**)&gq, g_q);
    cudaGetSymbolAddress((void**)&gk, g_k);
    cudaGetSymbolAddress((void**)&gv, g_v);
    cudaGetSymbolAddress((void**)&ga, g_attn);

    cudaFuncSetAttribute(gemm_tc,
                         cudaFuncAttributeMaxDynamicSharedMemorySize, GEMM_SMEM);
    const int attn_smem = (4096 * 3 + 64 * PS_LD) * (int)sizeof(float);
    cudaFuncSetAttribute(attn_kernel,
                         cudaFuncAttributeMaxDynamicSharedMemorySize, attn_smem);

    dim3 gemmGrid(DMODEL / 128, (BATCH * SEQ) / 128);  // (8, 64)
    gemm_tc<<<gemmGrid, 256, GEMM_SMEM>>>(q, wq_w, wq_b, gq, 1);
    gemm_tc<<<gemmGrid, 256, GEMM_SMEM>>>(k, wk_w, wk_b, gk, 1);
    gemm_tc<<<gemmGrid, 256, GEMM_SMEM>>>(v, wv_w, wv_b, gv, 1);

    dim3 attnGrid(SEQ / 64, BATCH * HEADS);            // (32, 64)
    attn_kernel<<<attnGrid, 256, attn_smem>>>(gq, gk, gv, ga);

    gemm_tc<<<gemmGrid, 256, GEMM_SMEM>>>(ga, dw, db, out, 0);
}

// round 8
// speedup vs baseline: 3.0905x; 1.6189x over previous
#include <cuda_runtime.h>
#include <cuda_bf16.h>
#include <cstdint>
#include <math.h>

#define BATCH 4
#define SEQ 2048
#define DMODEL 1024
#define HEADS 16
#define DEPTH 64

// Scratch (module-load allocated; no runtime allocation).
__device__ float g_q[BATCH * SEQ * DMODEL];
__device__ float g_k[BATCH * SEQ * DMODEL];
__device__ float g_v[BATCH * SEQ * DMODEL];
__device__ float g_attn[BATCH * SEQ * DMODEL];

// ===========================================================================
// Shared helpers (mma.sync m16n8k16 bf16 — frag layouts HW-verified in R6)
// ===========================================================================
__device__ __forceinline__ void mma_bf16(float* c, uint32_t a0, uint32_t a1,
                                         uint32_t a2, uint32_t a3,
                                         uint32_t b0, uint32_t b1) {
    asm volatile(
        "mma.sync.aligned.m16n8k16.row.col.f32.bf16.bf16.f32 "
        "{%0,%1,%2,%3},{%4,%5,%6,%7},{%8,%9},{%0,%1,%2,%3};"
        : "+f"(c[0]), "+f"(c[1]), "+f"(c[2]), "+f"(c[3])
        : "r"(a0), "r"(a1), "r"(a2), "r"(a3), "r"(b0), "r"(b1));
}

__device__ __forceinline__ float fast_ex2(float x) {
    float r;
    asm("ex2.approx.f32 %0, %1;" : "=f"(r) : "f"(x));
    return r;
}

__device__ __forceinline__ uint32_t pack2_hi(float x, float y) {
    __nv_bfloat162 t;
    t.x = __float2bfloat16(x);
    t.y = __float2bfloat16(y);
    return *(uint32_t*)&t;
}
__device__ __forceinline__ uint32_t pack2_lo(float x, float y,
                                             uint32_t hipair) {
    __nv_bfloat162 h = *(__nv_bfloat162*)&hipair;
    __nv_bfloat162 t;
    t.x = __float2bfloat16(x - __bfloat162float(h.x));
    t.y = __float2bfloat16(y - __bfloat162float(h.y));
    return *(uint32_t*)&t;
}

// ===========================================================================
// bf16 split-precision GEMM (unchanged from R6 — verified)
// ===========================================================================
#define BM 128
#define BN 128
#define BK 32
#define NCHUNK (DMODEL / BK)
#define SKS 40
#define PLANE (128 * SKS)
#define GEMM_SMEM (2 * 4 * PLANE * 2)

__device__ __forceinline__ void cvt_store(float4 x, __nv_bfloat16* hi,
                                          __nv_bfloat16* lo, int idx) {
    __nv_bfloat16 h0 = __float2bfloat16(x.x);
    __nv_bfloat16 h1 = __float2bfloat16(x.y);
    __nv_bfloat16 h2 = __float2bfloat16(x.z);
    __nv_bfloat16 h3 = __float2bfloat16(x.w);
    __nv_bfloat16 l0 = __float2bfloat16(x.x - __bfloat162float(h0));
    __nv_bfloat16 l1 = __float2bfloat16(x.y - __bfloat162float(h1));
    __nv_bfloat16 l2 = __float2bfloat16(x.z - __bfloat162float(h2));
    __nv_bfloat16 l3 = __float2bfloat16(x.w - __bfloat162float(h3));
    __nv_bfloat162 hp0; hp0.x = h0; hp0.y = h1;
    __nv_bfloat162 hp1; hp1.x = h2; hp1.y = h3;
    __nv_bfloat162 lp0; lp0.x = l0; lp0.y = l1;
    __nv_bfloat162 lp1; lp1.x = l2; lp1.y = l3;
    *(__nv_bfloat162*)(hi + idx)     = hp0;
    *(__nv_bfloat162*)(hi + idx + 2) = hp1;
    *(__nv_bfloat162*)(lo + idx)     = lp0;
    *(__nv_bfloat162*)(lo + idx + 2) = lp1;
}

__device__ __forceinline__ void store_c(float* __restrict__ C, int m, int n,
                                        float v0, float v1, int headSplit) {
    float2 t; t.x = v0; t.y = v1;
    if (headSplit) {
        const int b = m >> 11, s = m & (SEQ - 1);
        const int h = n >> 6, d = n & 63;
        *(float2*)&C[(((size_t)(b * HEADS + h) * SEQ + s) * DEPTH) + d] = t;
    } else {
        *(float2*)&C[(size_t)m * DMODEL + n] = t;
    }
}

__global__ __launch_bounds__(256, 1)
void gemm_tc(const float* __restrict__ A, const float* __restrict__ W,
             const float* __restrict__ bias, float* __restrict__ C,
             int headSplit)
{
    extern __shared__ __nv_bfloat16 sm[];
    const int tid = threadIdx.x;
    const int lane = tid & 31;
    const int wid = tid >> 5;
    const int wm = (wid >> 2) * 64;
    const int wn = (wid & 3) * 32;
    const int m0 = blockIdx.y * BM;
    const int n0 = blockIdx.x * BN;

    float acc[4][4][4];
    #pragma unroll
    for (int mi = 0; mi < 4; mi++)
        #pragma unroll
        for (int ni = 0; ni < 4; ni++)
            #pragma unroll
            for (int t = 0; t < 4; t++) acc[mi][ni][t] = 0.0f;

    {
        __nv_bfloat16* Ah = sm;
        __nv_bfloat16* Al = sm + PLANE;
        __nv_bfloat16* Bh = sm + 2 * PLANE;
        __nv_bfloat16* Bl = sm + 3 * PLANE;
        #pragma unroll
        for (int i = 0; i < 4; i++) {
            const int pos = tid + (i << 8);
            const int row = pos >> 3, f4 = pos & 7;
            float4 xa = *(const float4*)(A + (size_t)(m0 + row) * DMODEL + f4 * 4);
            float4 xb = *(const float4*)(W + (size_t)(n0 + row) * DMODEL + f4 * 4);
            cvt_store(xa, Ah, Al, row * SKS + f4 * 4);
            cvt_store(xb, Bh, Bl, row * SKS + f4 * 4);
        }
    }
    __syncthreads();

    float4 regA[4], regB[4];
    for (int c = 0; c < NCHUNK; c++) {
        const int s = c & 1;
        if (c + 1 < NCHUNK) {
            const int k0 = (c + 1) * BK;
            #pragma unroll
            for (int i = 0; i < 4; i++) {
                const int pos = tid + (i << 8);
                const int row = pos >> 3, f4 = pos & 7;
                regA[i] = *(const float4*)(A + (size_t)(m0 + row) * DMODEL + k0 + f4 * 4);
                regB[i] = *(const float4*)(W + (size_t)(n0 + row) * DMODEL + k0 + f4 * 4);
            }
        }

        const __nv_bfloat16* Ah = sm + (s * 4 + 0) * PLANE;
        const __nv_bfloat16* Al = sm + (s * 4 + 1) * PLANE;
        const __nv_bfloat16* Bh = sm + (s * 4 + 2) * PLANE;
        const __nv_bfloat16* Bl = sm + (s * 4 + 3) * PLANE;

        #pragma unroll
        for (int ks = 0; ks < BK; ks += 16) {
            const int col = ks + (lane & 3) * 2;
            uint32_t ah[4][4], al[4][4], bh[4][2], bl[4][2];
            #pragma unroll
            for (int mi = 0; mi < 4; mi++) {
                const int r = wm + mi * 16 + (lane >> 2);
                ah[mi][0] = *(const uint32_t*)&Ah[r * SKS + col];
                ah[mi][1] = *(const uint32_t*)&Ah[(r + 8) * SKS + col];
                ah[mi][2] = *(const uint32_t*)&Ah[r * SKS + col + 8];
                ah[mi][3] = *(const uint32_t*)&Ah[(r + 8) * SKS + col + 8];
                al[mi][0] = *(const uint32_t*)&Al[r * SKS + col];
                al[mi][1] = *(const uint32_t*)&Al[(r + 8) * SKS + col];
                al[mi][2] = *(const uint32_t*)&Al[r * SKS + col + 8];
                al[mi][3] = *(const uint32_t*)&Al[(r + 8) * SKS + col + 8];
            }
            #pragma unroll
            for (int ni = 0; ni < 4; ni++) {
                const int n = wn + ni * 8 + (lane >> 2);
                bh[ni][0] = *(const uint32_t*)&Bh[n * SKS + col];
                bh[ni][1] = *(const uint32_t*)&Bh[n * SKS + col + 8];
                bl[ni][0] = *(const uint32_t*)&Bl[n * SKS + col];
                bl[ni][1] = *(const uint32_t*)&Bl[n * SKS + col + 8];
            }
            #pragma unroll
            for (int mi = 0; mi < 4; mi++)
                #pragma unroll
                for (int ni = 0; ni < 4; ni++) {
                    mma_bf16(acc[mi][ni], ah[mi][0], ah[mi][1], ah[mi][2], ah[mi][3],
                             bh[ni][0], bh[ni][1]);
                    mma_bf16(acc[mi][ni], ah[mi][0], ah[mi][1], ah[mi][2], ah[mi][3],
                             bl[ni][0], bl[ni][1]);
                    mma_bf16(acc[mi][ni], al[mi][0], al[mi][1], al[mi][2], al[mi][3],
                             bh[ni][0], bh[ni][1]);
                }
        }
        __syncthreads();
        if (c + 1 < NCHUNK) {
            const int s2 = (c + 1) & 1;
            __nv_bfloat16* Ah2 = sm + (s2 * 4 + 0) * PLANE;
            __nv_bfloat16* Al2 = sm + (s2 * 4 + 1) * PLANE;
            __nv_bfloat16* Bh2 = sm + (s2 * 4 + 2) * PLANE;
            __nv_bfloat16* Bl2 = sm + (s2 * 4 + 3) * PLANE;
            #pragma unroll
            for (int i = 0; i < 4; i++) {
                const int pos = tid + (i << 8);
                const int row = pos >> 3, f4 = pos & 7;
                cvt_store(regA[i], Ah2, Al2, row * SKS + f4 * 4);
                cvt_store(regB[i], Bh2, Bl2, row * SKS + f4 * 4);
            }
            __syncthreads();
        }
    }

    #pragma unroll
    for (int mi = 0; mi < 4; mi++) {
        const int r = m0 + wm + mi * 16 + (lane >> 2);
        #pragma unroll
        for (int ni = 0; ni < 4; ni++) {
            const int n = n0 + wn + ni * 8 + (lane & 3) * 2;
            const float b0 = bias[n], b1 = bias[n + 1];
            store_c(C, r,     n, acc[mi][ni][0] + b0, acc[mi][ni][1] + b1, headSplit);
            store_c(C, r + 8, n, acc[mi][ni][2] + b0, acc[mi][ni][3] + b1, headSplit);
        }
    }
}

// ===========================================================================
// Tensor-core flash attention, causal, split-bf16 (3-product) QK^T and PV.
// Grid (32 qtiles, 64 bh), 128 threads = 4 warps; warp w owns q-rows w*16..+15.
// smem: Kh/Kl [64 s][SLD d], Vh/Vl [64 s][SLD d] (natural layout).
// Q frags hoisted to registers once per CTA. P stays in registers
// (S C-frag layout == PV A-frag layout; no shuffles).
// ===========================================================================
#define SLD 72
#define ATTN_SMEM (4 * 64 * SLD * 2)   // 36864 B

__global__ __launch_bounds__(128) void attn_mma(
    const float* __restrict__ Q, const float* __restrict__ K,
    const float* __restrict__ V, float* __restrict__ O)
{
    extern __shared__ __nv_bfloat16 sms[];
    __nv_bfloat16* Kh = sms;
    __nv_bfloat16* Kl = sms + 64 * SLD;
    __nv_bfloat16* Vh = sms + 2 * 64 * SLD;
    __nv_bfloat16* Vl = sms + 3 * 64 * SLD;
    const unsigned short* VhU = (const unsigned short*)Vh;
    const unsigned short* VlU = (const unsigned short*)Vl;

    const int tid = threadIdx.x;
    const int lane = tid & 31;
    const int wid = tid >> 5;      // 0..3
    const int g = lane >> 2;       // 0..7  (row within frag)
    const int qq = lane & 3;       // 0..3  (col pair selector)
    const int qt = blockIdx.x;
    const int bh = blockIdx.y;
    const int qbase = qt * 64;

    const float* Qb = Q + (size_t)bh * SEQ * DEPTH;
    const float* Kb = K + (size_t)bh * SEQ * DEPTH;
    const float* Vb = V + (size_t)bh * SEQ * DEPTH;

    // ---- hoist Q fragments (rows r0, r0+8; 4 k-chunks of depth) ----
    uint32_t qh[4][4], ql[4][4];
    {
        const int r0 = qbase + wid * 16 + g;
        #pragma unroll
        for (int kd = 0; kd < 4; kd++) {
            const int c = kd * 16 + qq * 2;
            float2 x0 = *(const float2*)(Qb + (size_t)r0 * DEPTH + c);
            float2 x1 = *(const float2*)(Qb + (size_t)(r0 + 8) * DEPTH + c);
            float2 x2 = *(const float2*)(Qb + (size_t)r0 * DEPTH + c + 8);
            float2 x3 = *(const float2*)(Qb + (size_t)(r0 + 8) * DEPTH + c + 8);
            qh[kd][0] = pack2_hi(x0.x, x0.y); ql[kd][0] = pack2_lo(x0.x, x0.y, qh[kd][0]);
            qh[kd][1] = pack2_hi(x1.x, x1.y); ql[kd][1] = pack2_lo(x1.x, x1.y, qh[kd][1]);
            qh[kd][2] = pack2_hi(x2.x, x2.y); ql[kd][2] = pack2_lo(x2.x, x2.y, qh[kd][2]);
            qh[kd][3] = pack2_hi(x3.x, x3.y); ql[kd][3] = pack2_lo(x3.x, x3.y, qh[kd][3]);
        }
    }

    float m0 = -INFINITY, m1 = -INFINITY, l0 = 0.0f, l1 = 0.0f;
    float oac[8][4];
    #pragma unroll
    for (int nj = 0; nj < 8; nj++)
        #pragma unroll
        for (int t = 0; t < 4; t++) oac[nj][t] = 0.0f;

    const float fscale = 0.125f * 1.4426950408889634f;   // scale * log2(e)

    for (int kt = 0; kt <= qt; kt++) {
        __syncthreads();
        // ---- load K,V tiles -> split bf16 smem (natural [s][d]) ----
        #pragma unroll
        for (int i = 0; i < 8; i++) {
            const int pos = tid + (i << 7);
            const int srow = pos >> 4;
            const int f4 = pos & 15;
            float4 kx = *(const float4*)(Kb + (size_t)(kt * 64 + srow) * DEPTH + f4 * 4);
            float4 vx = *(const float4*)(Vb + (size_t)(kt * 64 + srow) * DEPTH + f4 * 4);
            cvt_store(kx, Kh, Kl, srow * SLD + f4 * 4);
            cvt_store(vx, Vh, Vl, srow * SLD + f4 * 4);
        }
        __syncthreads();

        // ---- S = Q K^T (split, 3 products) ----
        float sa[8][4];
        #pragma unroll
        for (int ni = 0; ni < 8; ni++)
            #pragma unroll
            for (int t = 0; t < 4; t++) sa[ni][t] = 0.0f;

        #pragma unroll
        for (int ni = 0; ni < 8; ni++) {
            const int n = ni * 8 + g;
            #pragma unroll
            for (int kd = 0; kd < 4; kd++) {
                const int c = kd * 16 + qq * 2;
                uint32_t kb0 = *(const uint32_t*)&Kh[n * SLD + c];
                uint32_t kb1 = *(const uint32_t*)&Kh[n * SLD + c + 8];
                uint32_t kl0 = *(const uint32_t*)&Kl[n * SLD + c];
                uint32_t kl1 = *(const uint32_t*)&Kl[n * SLD + c + 8];
                mma_bf16(sa[ni], qh[kd][0], qh[kd][1], qh[kd][2], qh[kd][3], kb0, kb1);
                mma_bf16(sa[ni], qh[kd][0], qh[kd][1], qh[kd][2], qh[kd][3], kl0, kl1);
                mma_bf16(sa[ni], ql[kd][0], ql[kd][1], ql[kd][2], ql[kd][3], kb0, kb1);
            }
        }

        // ---- causal mask on diagonal tile ----
        if (kt == qt) {
            const int rl0 = wid * 16 + g;
            const int rl1 = rl0 + 8;
            #pragma unroll
            for (int ni = 0; ni < 8; ni++) {
                const int cl = ni * 8 + qq * 2;
                if (cl > rl0)     sa[ni][0] = -1e30f;
                if (cl + 1 > rl0) sa[ni][1] = -1e30f;
                if (cl > rl1)     sa[ni][2] = -1e30f;
                if (cl + 1 > rl1) sa[ni][3] = -1e30f;
            }
        }

        // ---- online softmax (rows g and g+8; 4 lanes per row) ----
        float mx0 = -1e30f, mx1 = -1e30f;
        #pragma unroll
        for (int ni = 0; ni < 8; ni++) {
            mx0 = fmaxf(mx0, fmaxf(sa[ni][0], sa[ni][1]));
            mx1 = fmaxf(mx1, fmaxf(sa[ni][2], sa[ni][3]));
        }
        mx0 = fmaxf(mx0, __shfl_xor_sync(0xffffffffu, mx0, 1));
        mx0 = fmaxf(mx0, __shfl_xor_sync(0xffffffffu, mx0, 2));
        mx1 = fmaxf(mx1, __shfl_xor_sync(0xffffffffu, mx1, 1));
        mx1 = fmaxf(mx1, __shfl_xor_sync(0xffffffffu, mx1, 2));
        const float nm0 = fmaxf(m0, mx0);
        const float nm1 = fmaxf(m1, mx1);
        const float al0 = fast_ex2((m0 - nm0) * fscale);
        const float al1 = fast_ex2((m1 - nm1) * fscale);
        m0 = nm0; m1 = nm1;

        float sum0 = 0.0f, sum1 = 0.0f;
        uint32_t pah[4][4], pal[4][4];
        #pragma unroll
        for (int ni = 0; ni < 8; ni++) {
            float p0 = fast_ex2((sa[ni][0] - m0) * fscale);
            float p1 = fast_ex2((sa[ni][1] - m0) * fscale);
            float p2 = fast_ex2((sa[ni][2] - m1) * fscale);
            float p3 = fast_ex2((sa[ni][3] - m1) * fscale);
            sum0 += p0 + p1;
            sum1 += p2 + p3;
            const int ks = ni >> 1;
            const int hl = (ni & 1) << 1;    // 0 or 2
            pah[ks][hl + 0] = pack2_hi(p0, p1);
            pal[ks][hl + 0] = pack2_lo(p0, p1, pah[ks][hl + 0]);
            pah[ks][hl + 1] = pack2_hi(p2, p3);
            pal[ks][hl + 1] = pack2_lo(p2, p3, pah[ks][hl + 1]);
        }
        l0 = l0 * al0 + sum0;
        l1 = l1 * al1 + sum1;

        #pragma unroll
        for (int nj = 0; nj < 8; nj++) {
            oac[nj][0] *= al0; oac[nj][1] *= al0;
            oac[nj][2] *= al1; oac[nj][3] *= al1;
        }

        // ---- O += P V (split, 3 products); V b-frags via 16-bit LDS ----
        #pragma unroll
        for (int nj = 0; nj < 8; nj++) {
            const int n = nj * 8 + g;
            #pragma unroll
            for (int ks = 0; ks < 4; ks++) {
                const int c = ks * 16 + qq * 2;
                uint32_t vb0 = (uint32_t)VhU[c * SLD + n]
                             | ((uint32_t)VhU[(c + 1) * SLD + n] << 16);
                uint32_t vb1 = (uint32_t)VhU[(c + 8) * SLD + n]
                             | ((uint32_t)VhU[(c + 9) * SLD + n] << 16);
                uint32_t wl0 = (uint32_t)VlU[c * SLD + n]
                             | ((uint32_t)VlU[(c + 1) * SLD + n] << 16);
                uint32_t wl1 = (uint32_t)VlU[(c + 8) * SLD + n]
                             | ((uint32_t)VlU[(c + 9) * SLD + n] << 16);
                mma_bf16(oac[nj], pah[ks][0], pah[ks][1], pah[ks][2], pah[ks][3], vb0, vb1);
                mma_bf16(oac[nj], pah[ks][0], pah[ks][1], pah[ks][2], pah[ks][3], wl0, wl1);
                mma_bf16(oac[nj], pal[ks][0], pal[ks][1], pal[ks][2], pal[ks][3], vb0, vb1);
            }
        }
    }

    // ---- finalize: row-reduce l, normalize, write merged-head layout ----
    l0 += __shfl_xor_sync(0xffffffffu, l0, 1);
    l0 += __shfl_xor_sync(0xffffffffu, l0, 2);
    l1 += __shfl_xor_sync(0xffffffffu, l1, 1);
    l1 += __shfl_xor_sync(0xffffffffu, l1, 2);
    const float inv0 = 1.0f / l0;
    const float inv1 = 1.0f / l1;

    const int b = bh >> 4;
    const int h = bh & 15;
    const int r0 = qbase + wid * 16 + g;
    #pragma unroll
    for (int nj = 0; nj < 8; nj++) {
        const int d = h * DEPTH + nj * 8 + qq * 2;
        float2 t0; t0.x = oac[nj][0] * inv0; t0.y = oac[nj][1] * inv0;
        float2 t1; t1.x = oac[nj][2] * inv1; t1.y = oac[nj][3] * inv1;
        *(float2*)&O[((size_t)b * SEQ + r0) * DMODEL + d] = t0;
        *(float2*)&O[((size_t)b * SEQ + r0 + 8) * DMODEL + d] = t1;
    }
}

// ===========================================================================
extern "C" void kernel_launch(void* const* d_in, const int* in_sizes, int n_in,
                              void* d_out, int out_size)
{
    const float* q    = (const float*)d_in[0];
    const float* k    = (const float*)d_in[1];
    const float* v    = (const float*)d_in[2];
    const float* wq_w = (const float*)d_in[3];
    const float* wq_b = (const float*)d_in[4];
    const float* wk_w = (const float*)d_in[5];
    const float* wk_b = (const float*)d_in[6];
    const float* wv_w = (const float*)d_in[7];
    const float* wv_b = (const float*)d_in[8];
    const float* dw   = (const float*)d_in[9];
    const float* db   = (const float*)d_in[10];
    float* out = (float*)d_out;

    float *gq, *gk, *gv, *ga;
    cudaGetSymbolAddress((void**)&gq, g_q);
    cudaGetSymbolAddress((void**)&gk, g_k);
    cudaGetSymbolAddress((void**)&gv, g_v);
    cudaGetSymbolAddress((void**)&ga, g_attn);

    cudaFuncSetAttribute(gemm_tc,
                         cudaFuncAttributeMaxDynamicSharedMemorySize, GEMM_SMEM);
    cudaFuncSetAttribute(attn_mma,
                         cudaFuncAttributeMaxDynamicSharedMemorySize, ATTN_SMEM);

    dim3 gemmGrid(DMODEL / 128, (BATCH * SEQ) / 128);  // (8, 64)
    gemm_tc<<<gemmGrid, 256, GEMM_SMEM>>>(q, wq_w, wq_b, gq, 1);
    gemm_tc<<<gemmGrid, 256, GEMM_SMEM>>>(k, wk_w, wk_b, gk, 1);
    gemm_tc<<<gemmGrid, 256, GEMM_SMEM>>>(v, wv_w, wv_b, gv, 1);

    dim3 attnGrid(SEQ / 64, BATCH * HEADS);            // (32, 64)
    attn_mma<<<attnGrid, 128, ATTN_SMEM>>>(gq, gk, gv, ga);

    gemm_tc<<<gemmGrid, 256, GEMM_SMEM>>>(ga, dw, db, out, 0);
}

// round 9
// speedup vs baseline: 3.3684x; 1.0899x over previous
#include <cuda_runtime.h>
#include <cuda_bf16.h>
#include <cstdint>
#include <math.h>

#define BATCH 4
#define SEQ 2048
#define DMODEL 1024
#define HEADS 16
#define DEPTH 64
#define NELEM (BATCH * SEQ * DMODEL)   // 8388608
#define WELEM (DMODEL * DMODEL)        // 1048576

// ---- persistent bf16 hi/lo scratch (module-load allocated) ----
__device__ __nv_bfloat16 g_qh[NELEM], g_ql[NELEM];
__device__ __nv_bfloat16 g_kh[NELEM], g_kl[NELEM];
__device__ __nv_bfloat16 g_vh[NELEM], g_vl[NELEM];
__device__ __nv_bfloat16 g_wqh[WELEM], g_wql[WELEM];
__device__ __nv_bfloat16 g_wkh[WELEM], g_wkl[WELEM];
__device__ __nv_bfloat16 g_wvh[WELEM], g_wvl[WELEM];
__device__ __nv_bfloat16 g_wdh[WELEM], g_wdl[WELEM];
__device__ __nv_bfloat16 g_Qh[NELEM], g_Ql[NELEM];   // projected, [bh][s][64]
__device__ __nv_bfloat16 g_Kh[NELEM], g_Kl[NELEM];
__device__ __nv_bfloat16 g_Vh[NELEM], g_Vl[NELEM];
__device__ __nv_bfloat16 g_Oh[NELEM], g_Ol[NELEM];   // attn out, flat [m][1024]

// ===========================================================================
// helpers (m16n8k16 frag layouts HW-verified in R6/R8)
// ===========================================================================
__device__ __forceinline__ uint32_t smem_u32(const void* p) {
    uint32_t a;
    asm("{ .reg .u64 t; cvta.to.shared.u64 t, %1; cvt.u32.u64 %0, t; }"
        : "=r"(a) : "l"(p));
    return a;
}

__device__ __forceinline__ void mma_bf16(float* c, const uint32_t* a,
                                         uint32_t b0, uint32_t b1) {
    asm volatile(
        "mma.sync.aligned.m16n8k16.row.col.f32.bf16.bf16.f32 "
        "{%0,%1,%2,%3},{%4,%5,%6,%7},{%8,%9},{%0,%1,%2,%3};"
        : "+f"(c[0]), "+f"(c[1]), "+f"(c[2]), "+f"(c[3])
        : "r"(a[0]), "r"(a[1]), "r"(a[2]), "r"(a[3]), "r"(b0), "r"(b1));
}

__device__ __forceinline__ void ldsm_x4(uint32_t* r, uint32_t addr) {
    asm volatile("ldmatrix.sync.aligned.m8n8.x4.shared.b16 {%0,%1,%2,%3}, [%4];"
        : "=r"(r[0]), "=r"(r[1]), "=r"(r[2]), "=r"(r[3]) : "r"(addr));
}
__device__ __forceinline__ void ldsm_x4_t(uint32_t* r, uint32_t addr) {
    asm volatile("ldmatrix.sync.aligned.m8n8.x4.trans.shared.b16 {%0,%1,%2,%3}, [%4];"
        : "=r"(r[0]), "=r"(r[1]), "=r"(r[2]), "=r"(r[3]) : "r"(addr));
}

__device__ __forceinline__ float fast_ex2(float x) {
    float r;
    asm("ex2.approx.f32 %0, %1;" : "=f"(r) : "f"(x));
    return r;
}

__device__ __forceinline__ uint32_t pack2_hi(float x, float y) {
    __nv_bfloat162 t;
    t.x = __float2bfloat16(x);
    t.y = __float2bfloat16(y);
    return *(uint32_t*)&t;
}
__device__ __forceinline__ uint32_t pack2_lo(float x, float y, uint32_t hp) {
    __nv_bfloat162 h = *(__nv_bfloat162*)&hp;
    __nv_bfloat162 t;
    t.x = __float2bfloat16(x - __bfloat162float(h.x));
    t.y = __float2bfloat16(y - __bfloat162float(h.y));
    return *(uint32_t*)&t;
}

// ===========================================================================
// split: fp32 -> bf16 hi/lo planes
// ===========================================================================
__global__ __launch_bounds__(256) void split_pair(
    const float* __restrict__ in, __nv_bfloat16* __restrict__ hi,
    __nv_bfloat16* __restrict__ lo, int n4)
{
    const int i = blockIdx.x * 256 + threadIdx.x;
    if (i < n4) {
        float4 x = ((const float4*)in)[i];
        uint32_t h0 = pack2_hi(x.x, x.y);
        uint32_t h1 = pack2_hi(x.z, x.w);
        uint32_t l0 = pack2_lo(x.x, x.y, h0);
        uint32_t l1 = pack2_lo(x.z, x.w, h1);
        uint2 hv; hv.x = h0; hv.y = h1;
        uint2 lv; lv.x = l0; lv.y = l1;
        ((uint2*)hi)[i] = hv;
        ((uint2*)lo)[i] = lv;
    }
}

// ===========================================================================
// bf16 split GEMM: C = A*W^T + bias; A/W pre-split hi/lo bf16.
// 128x128x32 tiles, 256 thr, 8 warps 2x4, frag loads via ldmatrix.
// outMode 0: fp32 flat [m][1024];  1: bf16 hi/lo head-split [bh][s][64].
// ===========================================================================
#define BM 128
#define BN 128
#define BK 32
#define NCHUNK (DMODEL / BK)
#define SKS 40
#define PLANE (128 * SKS)
#define GEMM_SMEM (2 * 4 * PLANE * 2)   // 81920 B

__global__ __launch_bounds__(256, 1)
void gemm_bs(const __nv_bfloat16* __restrict__ Ahg, const __nv_bfloat16* __restrict__ Alg,
             const __nv_bfloat16* __restrict__ Whg, const __nv_bfloat16* __restrict__ Wlg,
             const float* __restrict__ bias,
             float* __restrict__ Cf,
             __nv_bfloat16* __restrict__ Chi, __nv_bfloat16* __restrict__ Clo,
             int outMode)
{
    extern __shared__ __nv_bfloat16 sm[];
    const int tid = threadIdx.x;
    const int lane = tid & 31;
    const int wid = tid >> 5;
    const int wm = (wid >> 2) * 64;
    const int wn = (wid & 3) * 32;
    const int m0 = blockIdx.y * BM;
    const int n0 = blockIdx.x * BN;
    const uint32_t sbase = smem_u32(sm);

    // ldsm lane-derived offsets
    const int mt = lane >> 3, rw = lane & 7;
    const int aro = (mt & 1) * 8 + rw;   // A: mat0/1 = rows, mat2/3 = +8 cols
    const int aco = (mt >> 1) * 8;
    const int bro = (mt >> 1) * 8 + rw;  // B: mat0/1 = cols c,c+8; mat2/3 = rows +8
    const int bco = (mt & 1) * 8;

    // copy-unit mapping: unit i: row=(tid>>2)+i*64, col8=(tid&3)*8
    const int crow = tid >> 2;
    const int cc8 = (tid & 3) * 8;

    float acc[4][4][4];
    #pragma unroll
    for (int mi = 0; mi < 4; mi++)
        #pragma unroll
        for (int ni = 0; ni < 4; ni++)
            #pragma unroll
            for (int t = 0; t < 4; t++) acc[mi][ni][t] = 0.0f;

    // chunk 0 -> stage 0
    #pragma unroll
    for (int i = 0; i < 2; i++) {
        const int row = crow + i * 64;
        const size_t ga = (size_t)(m0 + row) * DMODEL + cc8;
        const size_t gb = (size_t)(n0 + row) * DMODEL + cc8;
        const int so = row * SKS + cc8;
        *(uint4*)&sm[0 * PLANE + so] = *(const uint4*)&Ahg[ga];
        *(uint4*)&sm[1 * PLANE + so] = *(const uint4*)&Alg[ga];
        *(uint4*)&sm[2 * PLANE + so] = *(const uint4*)&Whg[gb];
        *(uint4*)&sm[3 * PLANE + so] = *(const uint4*)&Wlg[gb];
    }
    __syncthreads();

    uint4 rA[2], rB[2], rC[2], rD[2];
    for (int c = 0; c < NCHUNK; c++) {
        const int s = c & 1;
        if (c + 1 < NCHUNK) {
            const int k0 = (c + 1) * BK;
            #pragma unroll
            for (int i = 0; i < 2; i++) {
                const int row = crow + i * 64;
                const size_t ga = (size_t)(m0 + row) * DMODEL + k0 + cc8;
                const size_t gb = (size_t)(n0 + row) * DMODEL + k0 + cc8;
                rA[i] = *(const uint4*)&Ahg[ga];
                rB[i] = *(const uint4*)&Alg[ga];
                rC[i] = *(const uint4*)&Whg[gb];
                rD[i] = *(const uint4*)&Wlg[gb];
            }
        }
        const uint32_t pAh = sbase + (uint32_t)(s * 4 + 0) * PLANE * 2;
        const uint32_t pAl = sbase + (uint32_t)(s * 4 + 1) * PLANE * 2;
        const uint32_t pWh = sbase + (uint32_t)(s * 4 + 2) * PLANE * 2;
        const uint32_t pWl = sbase + (uint32_t)(s * 4 + 3) * PLANE * 2;

        #pragma unroll
        for (int ks = 0; ks < BK; ks += 16) {
            uint32_t ah[4][4], al[4][4], bh[2][4], bl[2][4];
            #pragma unroll
            for (int mi = 0; mi < 4; mi++) {
                const uint32_t off =
                    (uint32_t)((wm + mi * 16 + aro) * SKS + ks + aco) * 2;
                ldsm_x4(ah[mi], pAh + off);
                ldsm_x4(al[mi], pAl + off);
            }
            #pragma unroll
            for (int nip = 0; nip < 2; nip++) {
                const uint32_t off =
                    (uint32_t)((wn + nip * 16 + bro) * SKS + ks + bco) * 2;
                ldsm_x4(bh[nip], pWh + off);
                ldsm_x4(bl[nip], pWl + off);
            }
            #pragma unroll
            for (int mi = 0; mi < 4; mi++)
                #pragma unroll
                for (int ni = 0; ni < 4; ni++) {
                    const int nip = ni >> 1, o = (ni & 1) * 2;
                    mma_bf16(acc[mi][ni], ah[mi], bh[nip][o], bh[nip][o + 1]);
                    mma_bf16(acc[mi][ni], ah[mi], bl[nip][o], bl[nip][o + 1]);
                    mma_bf16(acc[mi][ni], al[mi], bh[nip][o], bh[nip][o + 1]);
                }
        }
        __syncthreads();
        if (c + 1 < NCHUNK) {
            __nv_bfloat16* base = sm + ((c + 1) & 1) * 4 * PLANE;
            #pragma unroll
            for (int i = 0; i < 2; i++) {
                const int so = (crow + i * 64) * SKS + cc8;
                *(uint4*)&base[0 * PLANE + so] = rA[i];
                *(uint4*)&base[1 * PLANE + so] = rB[i];
                *(uint4*)&base[2 * PLANE + so] = rC[i];
                *(uint4*)&base[3 * PLANE + so] = rD[i];
            }
            __syncthreads();
        }
    }

    // epilogue
    #pragma unroll
    for (int mi = 0; mi < 4; mi++) {
        const int r = m0 + wm + mi * 16 + (lane >> 2);
        #pragma unroll
        for (int ni = 0; ni < 4; ni++) {
            const int n = n0 + wn + ni * 8 + (lane & 3) * 2;
            const float b0 = bias[n], b1 = bias[n + 1];
            const float v00 = acc[mi][ni][0] + b0, v01 = acc[mi][ni][1] + b1;
            const float v10 = acc[mi][ni][2] + b0, v11 = acc[mi][ni][3] + b1;
            if (outMode == 0) {
                float2 t0; t0.x = v00; t0.y = v01;
                float2 t1; t1.x = v10; t1.y = v11;
                *(float2*)&Cf[(size_t)r * DMODEL + n] = t0;
                *(float2*)&Cf[(size_t)(r + 8) * DMODEL + n] = t1;
            } else {
                const int bb = r >> 11, ss = r & (SEQ - 1);
                const int hh = n >> 6, dd = n & 63;
                const size_t o0 =
                    ((size_t)(bb * HEADS + hh) * SEQ + ss) * DEPTH + dd;
                const size_t o1 = o0 + 8 * DEPTH;
                const uint32_t h0 = pack2_hi(v00, v01);
                const uint32_t l0 = pack2_lo(v00, v01, h0);
                const uint32_t h1 = pack2_hi(v10, v11);
                const uint32_t l1 = pack2_lo(v10, v11, h1);
                *(uint32_t*)&Chi[o0] = h0; *(uint32_t*)&Clo[o0] = l0;
                *(uint32_t*)&Chi[o1] = h1; *(uint32_t*)&Clo[o1] = l1;
            }
        }
    }
}

// ===========================================================================
// Tensor-core flash attention on pre-split bf16 planes. No conversions in
// the hot loop; K frags via ldmatrix, V frags via ldmatrix.trans.
// Grid (32, 64) with qt REVERSED for causal load balance; 128 threads.
// ===========================================================================
#define SLD 72
#define ATTN_SMEM (4 * 64 * SLD * 2)   // 36864 B

__global__ __launch_bounds__(128) void attn_mma2()
{
    extern __shared__ __nv_bfloat16 sms[];
    const int tid = threadIdx.x;
    const int lane = tid & 31;
    const int wid = tid >> 5;
    const int g = lane >> 2;
    const int qq = lane & 3;
    const int qt = (int)gridDim.x - 1 - (int)blockIdx.x;   // heavy tiles first
    const int bh = blockIdx.y;
    const int qbase = qt * 64;
    const size_t bhoff = (size_t)bh * SEQ * DEPTH;
    const uint32_t sK = smem_u32(sms);
    const uint32_t PBYTES = 64 * SLD * 2;

    const int mt = lane >> 3, rw = lane & 7;
    const int k_ro = (mt >> 1) * 8 + rw;   // K non-trans
    const int k_co = (mt & 1) * 8;
    const int v_ro = (mt & 1) * 8 + rw;    // V trans
    const int v_co = (mt >> 1) * 8;

    // Q frags straight from global hi/lo planes
    uint32_t qh[4][4], ql[4][4];
    {
        const size_t r0 = bhoff + (size_t)(qbase + wid * 16 + g) * DEPTH;
        const size_t r1 = r0 + 8 * DEPTH;
        #pragma unroll
        for (int kd = 0; kd < 4; kd++) {
            const int c = kd * 16 + qq * 2;
            qh[kd][0] = *(const uint32_t*)&g_Qh[r0 + c];
            qh[kd][1] = *(const uint32_t*)&g_Qh[r1 + c];
            qh[kd][2] = *(const uint32_t*)&g_Qh[r0 + c + 8];
            qh[kd][3] = *(const uint32_t*)&g_Qh[r1 + c + 8];
            ql[kd][0] = *(const uint32_t*)&g_Ql[r0 + c];
            ql[kd][1] = *(const uint32_t*)&g_Ql[r1 + c];
            ql[kd][2] = *(const uint32_t*)&g_Ql[r0 + c + 8];
            ql[kd][3] = *(const uint32_t*)&g_Ql[r1 + c + 8];
        }
    }

    float m0 = -INFINITY, m1 = -INFINITY, l0 = 0.0f, l1 = 0.0f;
    float oac[8][4];
    #pragma unroll
    for (int nj = 0; nj < 8; nj++)
        #pragma unroll
        for (int t = 0; t < 4; t++) oac[nj][t] = 0.0f;

    const float fscale = 0.125f * 1.4426950408889634f;

    for (int kt = 0; kt <= qt; kt++) {
        __syncthreads();
        // tile fill: pure 16B copies, 4 planes
        #pragma unroll
        for (int i = 0; i < 4; i++) {
            const int u = tid + i * 128;
            const int row = u >> 3, c8 = (u & 7) * 8;
            const size_t gsrc = bhoff + (size_t)(kt * 64 + row) * DEPTH + c8;
            const int so = row * SLD + c8;
            *(uint4*)&sms[0 * 64 * SLD + so] = *(const uint4*)&g_Kh[gsrc];
            *(uint4*)&sms[1 * 64 * SLD + so] = *(const uint4*)&g_Kl[gsrc];
            *(uint4*)&sms[2 * 64 * SLD + so] = *(const uint4*)&g_Vh[gsrc];
            *(uint4*)&sms[3 * 64 * SLD + so] = *(const uint4*)&g_Vl[gsrc];
        }
        __syncthreads();

        // S = Q K^T
        float sa[8][4];
        #pragma unroll
        for (int ni = 0; ni < 8; ni++)
            #pragma unroll
            for (int t = 0; t < 4; t++) sa[ni][t] = 0.0f;

        #pragma unroll
        for (int kd = 0; kd < 4; kd++) {
            #pragma unroll
            for (int nip = 0; nip < 4; nip++) {
                const uint32_t off =
                    (uint32_t)((nip * 16 + k_ro) * SLD + kd * 16 + k_co) * 2;
                uint32_t kh4[4], kl4[4];
                ldsm_x4(kh4, sK + off);
                ldsm_x4(kl4, sK + PBYTES + off);
                const int n0i = nip * 2;
                mma_bf16(sa[n0i], qh[kd], kh4[0], kh4[1]);
                mma_bf16(sa[n0i], qh[kd], kl4[0], kl4[1]);
                mma_bf16(sa[n0i], ql[kd], kh4[0], kh4[1]);
                mma_bf16(sa[n0i + 1], qh[kd], kh4[2], kh4[3]);
                mma_bf16(sa[n0i + 1], qh[kd], kl4[2], kl4[3]);
                mma_bf16(sa[n0i + 1], ql[kd], kh4[2], kh4[3]);
            }
        }

        // causal mask (diagonal tile)
        if (kt == qt) {
            const int rl0 = wid * 16 + g;
            const int rl1 = rl0 + 8;
            #pragma unroll
            for (int ni = 0; ni < 8; ni++) {
                const int cl = ni * 8 + qq * 2;
                if (cl > rl0)     sa[ni][0] = -1e30f;
                if (cl + 1 > rl0) sa[ni][1] = -1e30f;
                if (cl > rl1)     sa[ni][2] = -1e30f;
                if (cl + 1 > rl1) sa[ni][3] = -1e30f;
            }
        }

        // online softmax (verified R8)
        float mx0 = -1e30f, mx1 = -1e30f;
        #pragma unroll
        for (int ni = 0; ni < 8; ni++) {
            mx0 = fmaxf(mx0, fmaxf(sa[ni][0], sa[ni][1]));
            mx1 = fmaxf(mx1, fmaxf(sa[ni][2], sa[ni][3]));
        }
        mx0 = fmaxf(mx0, __shfl_xor_sync(0xffffffffu, mx0, 1));
        mx0 = fmaxf(mx0, __shfl_xor_sync(0xffffffffu, mx0, 2));
        mx1 = fmaxf(mx1, __shfl_xor_sync(0xffffffffu, mx1, 1));
        mx1 = fmaxf(mx1, __shfl_xor_sync(0xffffffffu, mx1, 2));
        const float nm0 = fmaxf(m0, mx0);
        const float nm1 = fmaxf(m1, mx1);
        const float al0 = fast_ex2((m0 - nm0) * fscale);
        const float al1 = fast_ex2((m1 - nm1) * fscale);
        m0 = nm0; m1 = nm1;

        float sum0 = 0.0f, sum1 = 0.0f;
        uint32_t pah[4][4], pal[4][4];
        #pragma unroll
        for (int ni = 0; ni < 8; ni++) {
            const float p0 = fast_ex2((sa[ni][0] - m0) * fscale);
            const float p1 = fast_ex2((sa[ni][1] - m0) * fscale);
            const float p2 = fast_ex2((sa[ni][2] - m1) * fscale);
            const float p3 = fast_ex2((sa[ni][3] - m1) * fscale);
            sum0 += p0 + p1;
            sum1 += p2 + p3;
            const int ks = ni >> 1;
            const int hl = (ni & 1) << 1;
            pah[ks][hl + 0] = pack2_hi(p0, p1);
            pal[ks][hl + 0] = pack2_lo(p0, p1, pah[ks][hl + 0]);
            pah[ks][hl + 1] = pack2_hi(p2, p3);
            pal[ks][hl + 1] = pack2_lo(p2, p3, pah[ks][hl + 1]);
        }
        l0 = l0 * al0 + sum0;
        l1 = l1 * al1 + sum1;

        #pragma unroll
        for (int nj = 0; nj < 8; nj++) {
            oac[nj][0] *= al0; oac[nj][1] *= al0;
            oac[nj][2] *= al1; oac[nj][3] *= al1;
        }

        // O += P V  (V frags via ldmatrix.trans)
        #pragma unroll
        for (int ks = 0; ks < 4; ks++) {
            #pragma unroll
            for (int njp = 0; njp < 4; njp++) {
                const uint32_t off =
                    (uint32_t)((ks * 16 + v_ro) * SLD + njp * 16 + v_co) * 2;
                uint32_t vh4[4], vl4[4];
                ldsm_x4_t(vh4, sK + 2 * PBYTES + off);
                ldsm_x4_t(vl4, sK + 3 * PBYTES + off);
                const int nj0 = njp * 2;
                mma_bf16(oac[nj0], pah[ks], vh4[0], vh4[1]);
                mma_bf16(oac[nj0], pah[ks], vl4[0], vl4[1]);
                mma_bf16(oac[nj0], pal[ks], vh4[0], vh4[1]);
                mma_bf16(oac[nj0 + 1], pah[ks], vh4[2], vh4[3]);
                mma_bf16(oac[nj0 + 1], pah[ks], vl4[2], vl4[3]);
                mma_bf16(oac[nj0 + 1], pal[ks], vh4[2], vh4[3]);
            }
        }
    }

    // finalize: write hi/lo planes flat [m][1024] for final GEMM
    l0 += __shfl_xor_sync(0xffffffffu, l0, 1);
    l0 += __shfl_xor_sync(0xffffffffu, l0, 2);
    l1 += __shfl_xor_sync(0xffffffffu, l1, 1);
    l1 += __shfl_xor_sync(0xffffffffu, l1, 2);
    const float inv0 = 1.0f / l0;
    const float inv1 = 1.0f / l1;

    const int bb = bh >> 4;
    const int hh = bh & 15;
    const size_t r0m =
        (size_t)(bb * SEQ + qbase + wid * 16 + g) * DMODEL + hh * DEPTH;
    const size_t r1m = r0m + 8 * DMODEL;
    #pragma unroll
    for (int nj = 0; nj < 8; nj++) {
        const int d = nj * 8 + qq * 2;
        const float v0 = oac[nj][0] * inv0, v1 = oac[nj][1] * inv0;
        const float w0 = oac[nj][2] * inv1, w1 = oac[nj][3] * inv1;
        const uint32_t hp0 = pack2_hi(v0, v1);
        const uint32_t lp0 = pack2_lo(v0, v1, hp0);
        const uint32_t hp1 = pack2_hi(w0, w1);
        const uint32_t lp1 = pack2_lo(w0, w1, hp1);
        *(uint32_t*)&g_Oh[r0m + d] = hp0;
        *(uint32_t*)&g_Ol[r0m + d] = lp0;
        *(uint32_t*)&g_Oh[r1m + d] = hp1;
        *(uint32_t*)&g_Ol[r1m + d] = lp1;
    }
}

// ===========================================================================
extern "C" void kernel_launch(void* const* d_in, const int* in_sizes, int n_in,
                              void* d_out, int out_size)
{
    const float* q    = (const float*)d_in[0];
    const float* k    = (const float*)d_in[1];
    const float* v    = (const float*)d_in[2];
    const float* wq_w = (const float*)d_in[3];
    const float* wq_b = (const float*)d_in[4];
    const float* wk_w = (const float*)d_in[5];
    const float* wk_b = (const float*)d_in[6];
    const float* wv_w = (const float*)d_in[7];
    const float* wv_b = (const float*)d_in[8];
    const float* dw   = (const float*)d_in[9];
    const float* db   = (const float*)d_in[10];
    float* out = (float*)d_out;

    __nv_bfloat16 *qh, *ql, *kh, *kl, *vh, *vl;
    __nv_bfloat16 *wqh, *wql, *wkh, *wkl, *wvh, *wvl, *wdh, *wdl;
    __nv_bfloat16 *Qh, *Ql, *Kh, *Kl, *Vh, *Vl, *Oh, *Ol;
    cudaGetSymbolAddress((void**)&qh, g_qh);   cudaGetSymbolAddress((void**)&ql, g_ql);
    cudaGetSymbolAddress((void**)&kh, g_kh);   cudaGetSymbolAddress((void**)&kl, g_kl);
    cudaGetSymbolAddress((void**)&vh, g_vh);   cudaGetSymbolAddress((void**)&vl, g_vl);
    cudaGetSymbolAddress((void**)&wqh, g_wqh); cudaGetSymbolAddress((void**)&wql, g_wql);
    cudaGetSymbolAddress((void**)&wkh, g_wkh); cudaGetSymbolAddress((void**)&wkl, g_wkl);
    cudaGetSymbolAddress((void**)&wvh, g_wvh); cudaGetSymbolAddress((void**)&wvl, g_wvl);
    cudaGetSymbolAddress((void**)&wdh, g_wdh); cudaGetSymbolAddress((void**)&wdl, g_wdl);
    cudaGetSymbolAddress((void**)&Qh, g_Qh);   cudaGetSymbolAddress((void**)&Ql, g_Ql);
    cudaGetSymbolAddress((void**)&Kh, g_Kh);   cudaGetSymbolAddress((void**)&Kl, g_Kl);
    cudaGetSymbolAddress((void**)&Vh, g_Vh);   cudaGetSymbolAddress((void**)&Vl, g_Vl);
    cudaGetSymbolAddress((void**)&Oh, g_Oh);   cudaGetSymbolAddress((void**)&Ol, g_Ol);

    cudaFuncSetAttribute(gemm_bs,
                         cudaFuncAttributeMaxDynamicSharedMemorySize, GEMM_SMEM);
    cudaFuncSetAttribute(attn_mma2,
                         cudaFuncAttributeMaxDynamicSharedMemorySize, ATTN_SMEM);

    // splits
    const int n4i = NELEM / 4, n4w = WELEM / 4;
    split_pair<<<n4i / 256, 256>>>(q, qh, ql, n4i);
    split_pair<<<n4i / 256, 256>>>(k, kh, kl, n4i);
    split_pair<<<n4i / 256, 256>>>(v, vh, vl, n4i);
    split_pair<<<n4w / 256, 256>>>(wq_w, wqh, wql, n4w);
    split_pair<<<n4w / 256, 256>>>(wk_w, wkh, wkl, n4w);
    split_pair<<<n4w / 256, 256>>>(wv_w, wvh, wvl, n4w);
    split_pair<<<n4w / 256, 256>>>(dw, wdh, wdl, n4w);

    dim3 gemmGrid(DMODEL / 128, (BATCH * SEQ) / 128);  // (8, 64)
    gemm_bs<<<gemmGrid, 256, GEMM_SMEM>>>(qh, ql, wqh, wql, wq_b,
                                          nullptr, Qh, Ql, 1);
    gemm_bs<<<gemmGrid, 256, GEMM_SMEM>>>(kh, kl, wkh, wkl, wk_b,
                                          nullptr, Kh, Kl, 1);
    gemm_bs<<<gemmGrid, 256, GEMM_SMEM>>>(vh, vl, wvh, wvl, wv_b,
                                          nullptr, Vh, Vl, 1);

    dim3 attnGrid(SEQ / 64, BATCH * HEADS);            // (32, 64)
    attn_mma2<<<attnGrid, 128, ATTN_SMEM>>>();

    gemm_bs<<<gemmGrid, 256, GEMM_SMEM>>>(Oh, Ol, wdh, wdl, db,
                                          out, nullptr, nullptr, 0);
}